// round 1
// baseline (speedup 1.0000x reference)
#include <cuda_runtime.h>
#include <math.h>

#define BATCH   2
#define SEQ     2048
#define DMODEL  1024
#define NHEADS  16
#define DK      64
#define NTOK    (BATCH*SEQ)      /* 4096 */
#define E3      (3*DMODEL)       /* 3072 */

// Scratch (allocation-free rule: __device__ globals)
__device__ float g_qkv[(size_t)NTOK * E3];      // ~50 MB
__device__ float g_attn[(size_t)NTOK * DMODEL]; // ~16.8 MB

// ---------------------------------------------------------------------------
// SGEMM core: C[M,N] = A[M,K] * B[N,K]^T   (both A and B are K-contiguous)
// BM=BN=64, BK=32, 256 threads, 4x4 per-thread microtile.
// ---------------------------------------------------------------------------
__device__ __forceinline__ void gemm_nt_body(const float* __restrict__ A,
                                             const float* __restrict__ B,
                                             float* __restrict__ C,
                                             int M, int N, int K)
{
    __shared__ float As[32][68];
    __shared__ float Bs[32][68];

    const int tid = threadIdx.x;            // 0..255
    const int m0  = blockIdx.y * 64;
    const int n0  = blockIdx.x * 64;
    const int tm  = tid >> 4;               // 0..15
    const int tn  = tid & 15;               // 0..15

    float acc[4][4] = {};

    for (int k0 = 0; k0 < K; k0 += 32) {
        // Load A tile (64x32) and B tile (64x32), 2 float4 per thread each.
#pragma unroll
        for (int i = 0; i < 2; i++) {
            int idx = tid + i * 256;        // 0..511
            int row = idx >> 3;             // 0..63
            int c4  = (idx & 7) << 2;       // 0,4,...,28
            float4 a = *(const float4*)&A[(size_t)(m0 + row) * K + k0 + c4];
            As[c4 + 0][row] = a.x; As[c4 + 1][row] = a.y;
            As[c4 + 2][row] = a.z; As[c4 + 3][row] = a.w;
            float4 b = *(const float4*)&B[(size_t)(n0 + row) * K + k0 + c4];
            Bs[c4 + 0][row] = b.x; Bs[c4 + 1][row] = b.y;
            Bs[c4 + 2][row] = b.z; Bs[c4 + 3][row] = b.w;
        }
        __syncthreads();

#pragma unroll
        for (int k = 0; k < 32; k++) {
            float4 a4 = *(const float4*)&As[k][tm * 4];
            float4 b4 = *(const float4*)&Bs[k][tn * 4];
            float av[4] = {a4.x, a4.y, a4.z, a4.w};
            float bv[4] = {b4.x, b4.y, b4.z, b4.w};
#pragma unroll
            for (int i = 0; i < 4; i++)
#pragma unroll
                for (int j = 0; j < 4; j++)
                    acc[i][j] += av[i] * bv[j];
        }
        __syncthreads();
    }

#pragma unroll
    for (int i = 0; i < 4; i++) {
        float4 v = make_float4(acc[i][0], acc[i][1], acc[i][2], acc[i][3]);
        *(float4*)&C[(size_t)(m0 + tm * 4 + i) * N + n0 + tn * 4] = v;
    }
}

__global__ __launch_bounds__(256)
void qkv_gemm_kernel(const float* __restrict__ x, const float* __restrict__ w_qkv)
{
    gemm_nt_body(x, w_qkv, g_qkv, NTOK, E3, DMODEL);
}

__global__ __launch_bounds__(256)
void out_gemm_kernel(const float* __restrict__ w_o, float* __restrict__ out)
{
    gemm_nt_body(g_attn, w_o, out, NTOK, DMODEL, DMODEL);
}

// ---------------------------------------------------------------------------
// RoPE applied in-place to Q and K halves of g_qkv.
// One thread per (token, head, freq-pair) -> handles both q and k pairs.
// ---------------------------------------------------------------------------
__global__ void rope_kernel(const int* __restrict__ pos)
{
    int t = blockIdx.x * blockDim.x + threadIdx.x;
    const int total = NTOK * NHEADS * (DK / 2);
    if (t >= total) return;

    int i = t & 31;                  // freq index 0..31
    int h = (t >> 5) & (NHEADS - 1);
    int n = t >> 9;                  // token index 0..4095
    int s = n & (SEQ - 1);

    float p = (float)pos[s];
    // inv_freq = 10000^{-i/32}
    float inv = expf(-((float)i / 32.0f) * 9.2103403719761836f);
    float ang = p * inv;
    float sn, cs;
    sincosf(ang, &sn, &cs);

    float* q = &g_qkv[(size_t)n * E3 + h * DK + 2 * i];
    float q1 = q[0], q2 = q[1];
    q[0] = q1 * cs - q2 * sn;
    q[1] = q1 * sn + q2 * cs;

    float* k = q + DMODEL;
    float k1 = k[0], k2 = k[1];
    k[0] = k1 * cs - k2 * sn;
    k[1] = k1 * sn + k2 * cs;
}

// ---------------------------------------------------------------------------
// Causal flash attention, fp32.
// Grid: (S/64, NHEADS, BATCH). 64 threads/block; thread r owns query row r
// of the 64-row Q tile. K/V tiles of 64 rows streamed through smem.
// Scores staged as Ss[c][r] (conflict-free: uniform c, r = lane).
// ---------------------------------------------------------------------------
__global__ __launch_bounds__(64)
void attn_kernel()
{
    const int qt = blockIdx.x;
    const int h  = blockIdx.y;
    const int b  = blockIdx.z;
    const int r  = threadIdx.x;           // 0..63
    const int qrow = qt * 64 + r;

    __shared__ float Ks[64][64];
    __shared__ float Vs[64][64];
    __shared__ float Ss[64][64];          // [c][r]

    const float scale = 0.125f;           // 1/sqrt(64)

    // Load this thread's q row (pre-scaled) into registers.
    float4 q[16];
    const float* qptr = &g_qkv[((size_t)(b * SEQ) + qrow) * E3 + h * DK];
#pragma unroll
    for (int i = 0; i < 16; i++) {
        float4 v = *(const float4*)&qptr[4 * i];
        v.x *= scale; v.y *= scale; v.z *= scale; v.w *= scale;
        q[i] = v;
    }

    float4 o[16];
#pragma unroll
    for (int i = 0; i < 16; i++) o[i] = make_float4(0.f, 0.f, 0.f, 0.f);
    float m = -1e30f, l = 0.f;

    for (int kt = 0; kt <= qt; kt++) {
        __syncthreads();   // previous tile fully consumed before overwrite
        const float* kbase = &g_qkv[((size_t)(b * SEQ) + kt * 64) * E3 + DMODEL + h * DK];
        const float* vbase = kbase + DMODEL;
#pragma unroll
        for (int i = 0; i < 16; i++) {
            int idx = r + i * 64;          // 0..1023
            int row = idx >> 4;            // 0..63
            int c4  = (idx & 15) << 2;     // 0..60
            *(float4*)&Ks[row][c4] = *(const float4*)&kbase[(size_t)row * E3 + c4];
            *(float4*)&Vs[row][c4] = *(const float4*)&vbase[(size_t)row * E3 + c4];
        }
        __syncthreads();

        // Scores for this thread's row against all 64 keys of the tile.
        float tmax = -1e30f;
        const bool diag = (kt == qt);
#pragma unroll 4
        for (int c = 0; c < 64; c++) {
            float ax = 0.f, ay = 0.f, az = 0.f, aw = 0.f;
#pragma unroll
            for (int i = 0; i < 16; i++) {
                float4 kv = *(const float4*)&Ks[c][4 * i];  // broadcast across lanes
                ax += q[i].x * kv.x; ay += q[i].y * kv.y;
                az += q[i].z * kv.z; aw += q[i].w * kv.w;
            }
            float s = (ax + ay) + (az + aw);
            if (diag && c > r) s = -1e30f;
            tmax = fmaxf(tmax, s);
            Ss[c][r] = s;
        }

        float mnew = fmaxf(m, tmax);
        float corr = __expf(m - mnew);
        m = mnew;
        l *= corr;
#pragma unroll
        for (int i = 0; i < 16; i++) {
            o[i].x *= corr; o[i].y *= corr; o[i].z *= corr; o[i].w *= corr;
        }

#pragma unroll 2
        for (int c = 0; c < 64; c++) {
            float p = __expf(Ss[c][r] - m);
            l += p;
#pragma unroll
            for (int i = 0; i < 16; i++) {
                float4 v = *(const float4*)&Vs[c][4 * i];   // broadcast
                o[i].x += p * v.x; o[i].y += p * v.y;
                o[i].z += p * v.z; o[i].w += p * v.w;
            }
        }
    }

    float inv = 1.f / l;
    float* op = &g_attn[((size_t)(b * SEQ) + qrow) * DMODEL + h * DK];
#pragma unroll
    for (int i = 0; i < 16; i++) {
        float4 v = o[i];
        v.x *= inv; v.y *= inv; v.z *= inv; v.w *= inv;
        *(float4*)&op[4 * i] = v;
    }
}

// ---------------------------------------------------------------------------
extern "C" void kernel_launch(void* const* d_in, const int* in_sizes, int n_in,
                              void* d_out, int out_size)
{
    const float* x      = (const float*)d_in[0];
    const int*   pos    = (const int*)d_in[1];
    const float* w_qkv  = (const float*)d_in[2];
    const float* w_o    = (const float*)d_in[3];
    float*       out    = (float*)d_out;

    // 1) QKV projection: [4096,3072] = [4096,1024] x [3072,1024]^T
    {
        dim3 grid(E3 / 64, NTOK / 64);
        qkv_gemm_kernel<<<grid, 256>>>(x, w_qkv);
    }
    // 2) RoPE on q and k, in place
    {
        int total = NTOK * NHEADS * (DK / 2);
        rope_kernel<<<(total + 255) / 256, 256>>>(pos);
    }
    // 3) Causal flash attention
    {
        dim3 grid(SEQ / 64, NHEADS, BATCH);
        attn_kernel<<<grid, 64>>>();
    }
    // 4) Output projection: [4096,1024] = [4096,1024] x [1024,1024]^T
    {
        dim3 grid(DMODEL / 64, NTOK / 64);
        out_gemm_kernel<<<grid, 256>>>(w_o, out);
    }
}